// round 3
// baseline (speedup 1.0000x reference)
#include <cuda_runtime.h>
#include <math.h>

// Problem constants
#define Cn   256
#define Hn   128
#define Wn   128
#define Bn   2
#define HWn  (Hn*Wn)        // 16384
#define NPIX (Bn*HWn)       // 32768
#define NCn  80
#define NPn  9
#define Kdcn (9*Cn)         // 2304

typedef unsigned long long ull;

// ---------------- f32x2 helpers (sm_103a packed fp32) ----------------
__device__ __forceinline__ void fma2(ull &d, ull a, ull b) {
    asm("fma.rn.f32x2 %0, %1, %2, %0;" : "+l"(d) : "l"(a), "l"(b));
}
__device__ __forceinline__ ull dup2(float v) {
    ull r; asm("mov.b64 %0, {%1, %1};" : "=l"(r) : "f"(v)); return r;
}
__device__ __forceinline__ float2 unpk(ull v) {
    float2 f; asm("mov.b64 {%0, %1}, %2;" : "=f"(f.x), "=f"(f.y) : "l"(v)); return f;
}

// ---------------- scratch (device globals; no cudaMalloc allowed) ----------------
__device__ float g_bufA[Bn*Cn*Hn*Wn];
__device__ float g_bufB[Bn*Cn*Hn*Wn];
__device__ float g_cls [Bn*Cn*Hn*Wn];
__device__ float g_pts [Bn*Cn*Hn*Wn];
__device__ float g_off [Bn*27*HWn];
__device__ float g_samp[(size_t)Kdcn*NPIX];   // 302 MB im2col-like sampled tensor
__device__ float g_dcn [(size_t)Cn*NPIX];     // dcn output, layout [C][NPIX]

// =====================================================================
// conv3x3 (pad=1) direct conv, fp32 via f32x2.
// Block tile: 128 output channels x (8 rows x 16 cols) pixels.
// blockDim 256: tx = tid&15 (pixel column), ty = tid>>4 (oc-pair group).
// grid.x = Bn*(H/8)*(W/16) = 256, grid.y = C/128 = 2.
// =====================================================================
__global__ void __launch_bounds__(256, 2)
conv3x3_kernel(const float* __restrict__ in, const float* __restrict__ wgt,
               const float* __restrict__ bias, float* __restrict__ out, int do_relu)
{
    __shared__ __align__(16) float in_s[4][10][18];   // 4 ic x halo(10x18)
    __shared__ __align__(16) float w_s[9][4][128];    // tap x ic x oc

    const int tid = threadIdx.x;
    const int tx  = tid & 15;
    const int ty  = tid >> 4;
    const int tb  = blockIdx.x;
    const int tcx = tb & 7;           // W/16 = 8
    const int tcy = (tb >> 3) & 15;   // H/8 = 16
    const int bb  = tb >> 7;          // batch
    const int x0  = tcx * 16, y0 = tcy * 8;
    const int oc0 = blockIdx.y * 128;

    ull acc[4][8];
    #pragma unroll
    for (int j = 0; j < 4; j++)
        #pragma unroll
        for (int i = 0; i < 8; i++) acc[j][i] = 0ULL;

    for (int ic0 = 0; ic0 < Cn; ic0 += 4) {
        // load input halo (4 x 10 x 18 = 720 floats), zero-padded
        #pragma unroll
        for (int idx = tid; idx < 720; idx += 256) {
            int ic = idx / 180; int rem = idx - ic * 180;
            int r = rem / 18;   int c = rem - r * 18;
            int yy = y0 - 1 + r, xx = x0 - 1 + c;
            float v = 0.f;
            if (yy >= 0 && yy < Hn && xx >= 0 && xx < Wn)
                v = __ldg(&in[((size_t)(bb*Cn + ic0 + ic)*Hn + yy)*Wn + xx]);
            in_s[ic][r][c] = v;
        }
        // load weights (128 oc x 4 ic x 9 = 4608 floats)
        #pragma unroll
        for (int idx = tid; idx < 4608; idx += 256) {
            int oc = idx / 36; int rem = idx - oc * 36;
            int ic = rem / 9;  int tap = rem - ic * 9;
            w_s[tap][ic][oc] = __ldg(&wgt[((size_t)(oc0 + oc)*Cn + ic0 + ic)*9 + tap]);
        }
        __syncthreads();

        #pragma unroll
        for (int ic = 0; ic < 4; ic++) {
            #pragma unroll
            for (int ky = 0; ky < 3; ky++) {
                #pragma unroll
                for (int kx = 0; kx < 3; kx++) {
                    const int tap = ky*3 + kx;
                    const float* ibase = &in_s[ic][ky][tx + kx];
                    ull a[8];
                    #pragma unroll
                    for (int i = 0; i < 8; i++) a[i] = dup2(ibase[i*18]);
                    const float* wbase = &w_s[tap][ic][ty*2];
                    ull wp[4];
                    #pragma unroll
                    for (int j = 0; j < 4; j++)
                        wp[j] = *reinterpret_cast<const ull*>(wbase + 32*j);
                    #pragma unroll
                    for (int j = 0; j < 4; j++)
                        #pragma unroll
                        for (int i = 0; i < 8; i++) fma2(acc[j][i], wp[j], a[i]);
                }
            }
        }
        __syncthreads();
    }

    // epilogue: bias + optional relu
    #pragma unroll
    for (int j = 0; j < 4; j++) {
        int oc = oc0 + ty*2 + 32*j;
        float b0 = bias[oc], b1 = bias[oc + 1];
        #pragma unroll
        for (int i = 0; i < 8; i++) {
            float2 v = unpk(acc[j][i]);
            float r0 = v.x + b0, r1 = v.y + b1;
            if (do_relu) { r0 = fmaxf(r0, 0.f); r1 = fmaxf(r1, 0.f); }
            int y = y0 + i, x = x0 + tx;
            out[((size_t)(bb*Cn + oc    )*Hn + y)*Wn + x] = r0;
            out[((size_t)(bb*Cn + oc + 1)*Hn + y)*Wn + x] = r1;
        }
    }
}

// =====================================================================
// GEMM for deformable conv: out[o][p] = sum_K W[o][K] * S[K][p],
// K = 2304 (c*9+tap), p over NPIX. Output layout [C][NPIX], relu applied.
// Block tile 128 oc x 128 px, grid (NPIX/128=256, 2).
// =====================================================================
__global__ void __launch_bounds__(256, 2)
dcn_gemm_kernel(const float* __restrict__ S, const float* __restrict__ wgt,
                float* __restrict__ out)
{
    __shared__ __align__(16) float s_s[8][128];
    __shared__ __align__(16) float w_s[8][128];

    const int tid = threadIdx.x;
    const int tx  = tid & 15;
    const int ty  = tid >> 4;
    const int p0  = blockIdx.x * 128;
    const int oc0 = blockIdx.y * 128;

    ull acc[4][8];
    #pragma unroll
    for (int j = 0; j < 4; j++)
        #pragma unroll
        for (int i = 0; i < 8; i++) acc[j][i] = 0ULL;

    for (int k0 = 0; k0 < Kdcn; k0 += 8) {
        #pragma unroll
        for (int idx = tid; idx < 1024; idx += 256) {
            int kk = idx >> 7, p = idx & 127;
            s_s[kk][p] = __ldg(&S[(size_t)(k0 + kk)*NPIX + p0 + p]);
        }
        #pragma unroll
        for (int idx = tid; idx < 1024; idx += 256) {
            int oc = idx >> 3, kk = idx & 7;
            w_s[kk][oc] = __ldg(&wgt[(size_t)(oc0 + oc)*Kdcn + k0 + kk]);
        }
        __syncthreads();

        #pragma unroll
        for (int kk = 0; kk < 8; kk++) {
            ull a[8];
            #pragma unroll
            for (int i = 0; i < 8; i++) a[i] = dup2(s_s[kk][tx + 16*i]);
            const float* wbase = &w_s[kk][ty*2];
            ull wp[4];
            #pragma unroll
            for (int j = 0; j < 4; j++)
                wp[j] = *reinterpret_cast<const ull*>(wbase + 32*j);
            #pragma unroll
            for (int j = 0; j < 4; j++)
                #pragma unroll
                for (int i = 0; i < 8; i++) fma2(acc[j][i], wp[j], a[i]);
        }
        __syncthreads();
    }

    #pragma unroll
    for (int j = 0; j < 4; j++) {
        int oc = oc0 + ty*2 + 32*j;
        #pragma unroll
        for (int i = 0; i < 8; i++) {
            float2 v = unpk(acc[j][i]);
            int p = p0 + tx + 16*i;
            out[(size_t)oc      *NPIX + p] = fmaxf(v.x, 0.f);
            out[(size_t)(oc + 1)*NPIX + p] = fmaxf(v.y, 0.f);
        }
    }
}

// =====================================================================
// Bilinear sampling stage of deformable conv.
// One thread per (tap k, pixel): loops all 256 channels.
// samp layout: [(c*9+k)][pix], matching OIHW weight flattening o*(c*9+tap).
// grid = 9*NPIX/256 = 1152 blocks.
// =====================================================================
__global__ void __launch_bounds__(256)
dcn_sample_kernel(const float* __restrict__ feat, const float* __restrict__ off,
                  float* __restrict__ samp, int use_mask)
{
    int g = blockIdx.x * 256 + threadIdx.x;       // [0, 9*NPIX)
    int k   = g >> 15;                            // tap (pix fastest)
    int pix = g & (NPIX - 1);
    int b  = pix >> 14;
    int hw = pix & (HWn - 1);
    int y  = hw >> 7;
    int x  = hw & (Wn - 1);
    int ky = k / 3, kx = k - ky*3;

    float offy = off[((size_t)(b*27) + 2*k    )*HWn + hw];
    float offx = off[((size_t)(b*27) + 2*k + 1)*HWn + hw];
    float py = (float)y + (float)(ky - 1) + offy;
    float px = (float)x + (float)(kx - 1) + offx;

    float fy0 = floorf(py), fx0 = floorf(px);
    float ly = py - fy0, lx = px - fx0;
    bool vy0 = (fy0 >= 0.f)        && (fy0 <= (float)(Hn - 1));
    bool vy1 = (fy0 + 1.f >= 0.f)  && (fy0 + 1.f <= (float)(Hn - 1));
    bool vx0 = (fx0 >= 0.f)        && (fx0 <= (float)(Wn - 1));
    bool vx1 = (fx0 + 1.f >= 0.f)  && (fx0 + 1.f <= (float)(Wn - 1));

    float w00 = (1.f - ly)*(1.f - lx) * ((vy0 && vx0) ? 1.f : 0.f);
    float w01 = (1.f - ly)*lx         * ((vy0 && vx1) ? 1.f : 0.f);
    float w10 = ly*(1.f - lx)         * ((vy1 && vx0) ? 1.f : 0.f);
    float w11 = ly*lx                 * ((vy1 && vx1) ? 1.f : 0.f);

    if (use_mask) {
        float m = off[((size_t)(b*27) + 18 + k)*HWn + hw];
        w00 *= m; w01 *= m; w10 *= m; w11 *= m;
    }

    int iy0 = min(max((int)fy0,      0), Hn - 1);
    int iy1 = min(max((int)fy0 + 1,  0), Hn - 1);
    int ix0 = min(max((int)fx0,      0), Wn - 1);
    int ix1 = min(max((int)fx0 + 1,  0), Wn - 1);
    int i00 = iy0*Wn + ix0, i01 = iy0*Wn + ix1;
    int i10 = iy1*Wn + ix0, i11 = iy1*Wn + ix1;

    const float* fbase = feat + (size_t)b*Cn*HWn;
    #pragma unroll 4
    for (int c = 0; c < Cn; c++) {
        const float* fp = fbase + (size_t)c*HWn;
        float v = w00*__ldg(fp + i00) + w01*__ldg(fp + i01)
                + w10*__ldg(fp + i10) + w11*__ldg(fp + i11);
        samp[(size_t)(c*9 + k)*NPIX + pix] = v;
    }
}

// =====================================================================
// 1x1 conv, 27 outputs (pts_out_init). Input NCHW, output [(b*27+o)][hw].
// One thread per pixel computes all 27 channels. grid = NPIX/256 = 128.
// =====================================================================
__global__ void __launch_bounds__(256)
conv1x1_27_kernel(const float* __restrict__ in, const float* __restrict__ wgt,
                  const float* __restrict__ bias, float* __restrict__ out)
{
    __shared__ float ws[Cn*27];
    for (int idx = threadIdx.x; idx < Cn*27; idx += 256) {
        int o = idx >> 8, ic = idx & 255;
        ws[ic*27 + o] = wgt[(size_t)o*Cn + ic];
    }
    __syncthreads();

    int p  = blockIdx.x * 256 + threadIdx.x;
    int b  = p >> 14;
    int hw = p & (HWn - 1);

    float acc[27];
    #pragma unroll
    for (int o = 0; o < 27; o++) acc[o] = 0.f;

    const float* ip = in + (size_t)b*Cn*HWn + hw;
    for (int ic = 0; ic < Cn; ic++) {
        float v = __ldg(ip + (size_t)ic*HWn);
        #pragma unroll
        for (int o = 0; o < 27; o++) acc[o] += v * ws[ic*27 + o];
    }
    #pragma unroll
    for (int o = 0; o < 27; o++)
        out[((size_t)(b*27) + o)*HWn + hw] = acc[o] + bias[o];
}

// =====================================================================
// 1x1 conv, 80 outputs (cls head). Input layout [C][NPIX] (dcn output).
// grid (NPIX/256 = 128, 5 oc-groups of 16).
// =====================================================================
__global__ void __launch_bounds__(256)
conv1x1_cls_kernel(const float* __restrict__ in, const float* __restrict__ wgt,
                   const float* __restrict__ bias, float* __restrict__ out)
{
    __shared__ float ws[Cn*16];
    int g = blockIdx.y;
    for (int idx = threadIdx.x; idx < Cn*16; idx += 256) {
        int j = idx >> 8, ic = idx & 255;
        ws[ic*16 + j] = wgt[(size_t)(g*16 + j)*Cn + ic];
    }
    __syncthreads();

    int p  = blockIdx.x * 256 + threadIdx.x;
    int b  = p >> 14;
    int hw = p & (HWn - 1);

    float acc[16];
    #pragma unroll
    for (int j = 0; j < 16; j++) acc[j] = 0.f;

    for (int ic = 0; ic < Cn; ic++) {
        float v = __ldg(&in[(size_t)ic*NPIX + p]);
        #pragma unroll
        for (int j = 0; j < 16; j++) acc[j] += v * ws[ic*16 + j];
    }
    #pragma unroll
    for (int j = 0; j < 16; j++) {
        int oc = g*16 + j;
        out[((size_t)(b*NCn) + oc)*HWn + hw] = acc[j] + bias[oc];
    }
}

// =====================================================================
// Fused refine head: 1x1 conv (18 out) + add offset + mean/wh/reg epilogue.
// Input layout [C][NPIX]. Writes wh (B,2,H,W) and reg (B,2,H,W) into d_out.
// grid = 128.
// =====================================================================
__global__ void __launch_bounds__(256)
ref_fused_kernel(const float* __restrict__ in, const float* __restrict__ wgt,
                 const float* __restrict__ bias, const float* __restrict__ off,
                 float* __restrict__ dout)
{
    __shared__ float ws[Cn*18];
    for (int idx = threadIdx.x; idx < Cn*18; idx += 256) {
        int o = idx >> 8, ic = idx & 255;
        ws[ic*18 + o] = wgt[(size_t)o*Cn + ic];
    }
    __syncthreads();

    int p  = blockIdx.x * 256 + threadIdx.x;
    int b  = p >> 14;
    int hw = p & (HWn - 1);

    float acc[18];
    #pragma unroll
    for (int o = 0; o < 18; o++) acc[o] = 0.f;

    for (int ic = 0; ic < Cn; ic++) {
        float v = __ldg(&in[(size_t)ic*NPIX + p]);
        #pragma unroll
        for (int o = 0; o < 18; o++) acc[o] += v * ws[ic*18 + o];
    }

    float refine[18];
    #pragma unroll
    for (int o = 0; o < 18; o++)
        refine[o] = acc[o] + bias[o] + off[((size_t)(b*27) + o)*HWn + hw];

    float m0 = 0.f, m1 = 0.f;
    #pragma unroll
    for (int q = 0; q < 9; q++) { m0 += refine[2*q]; m1 += refine[2*q + 1]; }
    m0 *= (1.f/9.f); m1 *= (1.f/9.f);

    float wh0 = 0.f, wh1 = 0.f;
    #pragma unroll
    for (int q = 0; q < 9; q++) {
        wh0 = fmaxf(wh0, fabsf(refine[2*q]     + m0));
        wh1 = fmaxf(wh1, fabsf(refine[2*q + 1] + m1));
    }

    const size_t OUT_WH  = (size_t)Bn*NCn*HWn;          // 2621440
    const size_t OUT_REG = OUT_WH + (size_t)Bn*2*HWn;   // +65536
    dout[OUT_WH  + ((size_t)(b*2) + 0)*HWn + hw] = wh0;
    dout[OUT_WH  + ((size_t)(b*2) + 1)*HWn + hw] = wh1;
    dout[OUT_REG + ((size_t)(b*2) + 0)*HWn + hw] = m0;
    dout[OUT_REG + ((size_t)(b*2) + 1)*HWn + hw] = m1;
}

// =====================================================================
extern "C" void kernel_launch(void* const* d_in, const int* in_sizes, int n_in,
                              void* d_out, int out_size)
{
    const float* x           = (const float*)d_in[0];
    const float* cls_w0      = (const float*)d_in[1];
    const float* cls_b0      = (const float*)d_in[2];
    const float* reg_w0      = (const float*)d_in[3];
    const float* reg_b0      = (const float*)d_in[4];
    const float* cls_w1      = (const float*)d_in[5];
    const float* cls_b1      = (const float*)d_in[6];
    const float* reg_w1      = (const float*)d_in[7];
    const float* reg_b1      = (const float*)d_in[8];
    const float* cls_w2      = (const float*)d_in[9];
    const float* cls_b2      = (const float*)d_in[10];
    const float* reg_w2      = (const float*)d_in[11];
    const float* reg_b2      = (const float*)d_in[12];
    const float* init_conv_w = (const float*)d_in[13];
    const float* init_conv_b = (const float*)d_in[14];
    const float* init_out_w  = (const float*)d_in[15];
    const float* init_out_b  = (const float*)d_in[16];
    const float* dcn_cls_w   = (const float*)d_in[17];
    const float* cls_out_w   = (const float*)d_in[18];
    const float* cls_out_b   = (const float*)d_in[19];
    const float* dcn_ref_w   = (const float*)d_in[20];
    const float* ref_out_w   = (const float*)d_in[21];
    const float* ref_out_b   = (const float*)d_in[22];
    float* out = (float*)d_out;

    float *bufA, *bufB, *cls, *pts, *off, *samp, *dcn;
    cudaGetSymbolAddress((void**)&bufA, g_bufA);
    cudaGetSymbolAddress((void**)&bufB, g_bufB);
    cudaGetSymbolAddress((void**)&cls,  g_cls);
    cudaGetSymbolAddress((void**)&pts,  g_pts);
    cudaGetSymbolAddress((void**)&off,  g_off);
    cudaGetSymbolAddress((void**)&samp, g_samp);
    cudaGetSymbolAddress((void**)&dcn,  g_dcn);

    dim3 cgrid(256, 2);

    // cls tower
    conv3x3_kernel<<<cgrid, 256>>>(x,    cls_w0, cls_b0, bufA, 1);
    conv3x3_kernel<<<cgrid, 256>>>(bufA, cls_w1, cls_b1, bufB, 1);
    conv3x3_kernel<<<cgrid, 256>>>(bufB, cls_w2, cls_b2, cls,  1);
    // reg tower
    conv3x3_kernel<<<cgrid, 256>>>(x,    reg_w0, reg_b0, bufA, 1);
    conv3x3_kernel<<<cgrid, 256>>>(bufA, reg_w1, reg_b1, bufB, 1);
    conv3x3_kernel<<<cgrid, 256>>>(bufB, reg_w2, reg_b2, pts,  1);
    // init branch: conv3x3+relu then 1x1 -> 27 channels (offset 0..17, mask 18..26)
    conv3x3_kernel<<<cgrid, 256>>>(pts, init_conv_w, init_conv_b, bufA, 1);
    conv1x1_27_kernel<<<128, 256>>>(bufA, init_out_w, init_out_b, off);

    // cls dcn: sample (with mask) -> GEMM+relu -> 1x1 cls head into d_out
    dcn_sample_kernel<<<1152, 256>>>(cls, off, samp, 1);
    dcn_gemm_kernel<<<cgrid, 256>>>(samp, dcn_cls_w, dcn);
    conv1x1_cls_kernel<<<dim3(128, 5), 256>>>(dcn, cls_out_w, cls_out_b, out);

    // ref dcn: sample (no mask) -> GEMM+relu -> fused refine/wh/reg into d_out
    dcn_sample_kernel<<<1152, 256>>>(pts, off, samp, 0);
    dcn_gemm_kernel<<<cgrid, 256>>>(samp, dcn_ref_w, dcn);
    ref_fused_kernel<<<128, 256>>>(dcn, ref_out_w, ref_out_b, off, out);
}

// round 5
// speedup vs baseline: 4.4126x; 4.4126x over previous
#include <cuda_runtime.h>
#include <cuda_bf16.h>
#include <math.h>
#include <stdint.h>

#define Cn   256
#define Hn   128
#define Wn   128
#define Bn   2
#define HWn  (Hn*Wn)        // 16384
#define NPIX (Bn*HWn)       // 32768
#define NCn  80
#define Kdcn 2304
#define WSZ  (Cn*Kdcn)      // 589824
#define NCHUNK 72           // 2304/32

// stage layout (bytes): A rows padded to 40 bf16 (80B), B rows 136 bf16 (272B)
#define A_HI 0
#define A_LO 10240
#define B_HI 20480
#define B_LO 29184
#define STG  37888          // multiple of 128
#define SM_TOTAL (2*STG)    // 75776

__device__ __forceinline__ uint32_t smem_to_u32(const void* p) {
    uint32_t a;
    asm("{ .reg .u64 t; cvta.to.shared.u64 t, %1; cvt.u32.u64 %0, t; }" : "=r"(a) : "l"(p));
    return a;
}
__device__ __forceinline__ void ldsm4(uint32_t r[4], uint32_t addr) {
    asm volatile("ldmatrix.sync.aligned.m8n8.x4.shared.b16 {%0,%1,%2,%3}, [%4];"
        : "=r"(r[0]), "=r"(r[1]), "=r"(r[2]), "=r"(r[3]) : "r"(addr));
}
__device__ __forceinline__ void ldsm4t(uint32_t r[4], uint32_t addr) {
    asm volatile("ldmatrix.sync.aligned.m8n8.x4.trans.shared.b16 {%0,%1,%2,%3}, [%4];"
        : "=r"(r[0]), "=r"(r[1]), "=r"(r[2]), "=r"(r[3]) : "r"(addr));
}
__device__ __forceinline__ void mma16816(float d[4], const uint32_t a[4],
                                         uint32_t b0, uint32_t b1) {
    asm volatile(
        "mma.sync.aligned.m16n8k16.row.col.f32.bf16.bf16.f32 "
        "{%0,%1,%2,%3}, {%4,%5,%6,%7}, {%8,%9}, {%0,%1,%2,%3};"
        : "+f"(d[0]), "+f"(d[1]), "+f"(d[2]), "+f"(d[3])
        : "r"(a[0]), "r"(a[1]), "r"(a[2]), "r"(a[3]), "r"(b0), "r"(b1));
}

// ---------------- scratch ----------------
__device__ float g_bufA[Bn*Cn*HWn];
__device__ float g_bufB[Bn*Cn*HWn];
__device__ float g_cls [Bn*Cn*HWn];
__device__ float g_pts [Bn*Cn*HWn];
__device__ float g_off [Bn*27*HWn];
__device__ float g_dcn [(size_t)Cn*NPIX];
__device__ __align__(16) __nv_bfloat16 g_whi[9*WSZ];
__device__ __align__(16) __nv_bfloat16 g_wlo[9*WSZ];

// ---------------- weight split: OIHW fp32 -> [oc][tap*256+ic] bf16 hi/lo ----------------
__global__ void __launch_bounds__(256)
split_w_kernel(const float* __restrict__ w, __nv_bfloat16* __restrict__ hi,
               __nv_bfloat16* __restrict__ lo)
{
    int idx = blockIdx.x * 256 + threadIdx.x;   // < 589824
    int oc = idx / Kdcn, kp = idx - oc * Kdcn;
    int tap = kp >> 8, ic = kp & 255;
    float v = w[((size_t)oc*256 + ic)*9 + tap];
    __nv_bfloat16 h = __float2bfloat16(v);
    hi[idx] = h;
    lo[idx] = __float2bfloat16(v - __bfloat162float(h));
}

// ---------------- fused implicit-GEMM (mma.sync bf16 3-term) ----------------
// mode: 0 = conv3x3 pad1 (bias+relu, out NCHW)
//       1 = dcn with mask (relu, out [oc][NPIX])
//       2 = dcn no mask  (relu, out [oc][NPIX])
__global__ void __launch_bounds__(256, 2)
gemm_kernel(int mode, const float* __restrict__ feat,
            const __nv_bfloat16* __restrict__ whi, const __nv_bfloat16* __restrict__ wlo,
            const float* __restrict__ bias, const float* __restrict__ off,
            float* __restrict__ out)
{
    extern __shared__ __align__(128) char smem[];
    const uint32_t sbase = smem_to_u32(smem);
    const int tid  = threadIdx.x;
    const int wid  = tid >> 5, lane = tid & 31;
    const int nblk = blockIdx.x;
    const int b = nblk >> 7, y = nblk & 127;
    const int ocbase = blockIdx.y * 128;

    // warp tile position
    const int m0 = (wid & 3) * 32;      // 4 m-warps
    const int n0 = (wid >> 2) * 64;     // 2 n-warps

    // ldmatrix lane addressing
    const int aR = (lane & 7) + ((lane >> 3) & 1) * 8;  // row within 16
    const int aC = (lane >> 4) * 8;                     // k 0/8
    const int bR = lane & 15;                           // k within 16
    const int bC = (lane >> 4) * 8;                     // px 0/8

    // loader mapping
    const int p = tid & 127, half = tid >> 7;
    const int arow = tid >> 1, aseg = tid & 1;

    float acc[16][4];
    #pragma unroll
    for (int i = 0; i < 16; i++)
        #pragma unroll
        for (int j = 0; j < 4; j++) acc[i][j] = 0.f;

    // ---- loader (lambda) ----
    auto load_chunk = [&](int stg, int cc) {
        char* s = smem + stg * STG;
        // A: weights 128oc x 32k hi+lo
        {
            size_t gi = (size_t)(ocbase + arow) * Kdcn + cc * 32 + aseg * 16;
            uint4 h0 = *reinterpret_cast<const uint4*>(whi + gi);
            uint4 h1 = *reinterpret_cast<const uint4*>(whi + gi + 8);
            uint4 l0 = *reinterpret_cast<const uint4*>(wlo + gi);
            uint4 l1 = *reinterpret_cast<const uint4*>(wlo + gi + 8);
            uint32_t so = (uint32_t)(arow * 80 + aseg * 32);
            *reinterpret_cast<uint4*>(s + A_HI + so)      = h0;
            *reinterpret_cast<uint4*>(s + A_HI + so + 16) = h1;
            *reinterpret_cast<uint4*>(s + A_LO + so)      = l0;
            *reinterpret_cast<uint4*>(s + A_LO + so + 16) = l1;
        }
        // B: activations 32k x 128px hi+lo
        const int tap = cc >> 3;
        const int icb = (cc & 7) * 32 + half * 16;
        const int ky = tap / 3 - 1, kx = tap % 3 - 1;

        if (mode == 0) {
            int yy = y + ky, xx = p + kx;
            bool ok = (yy >= 0 && yy < Hn && xx >= 0 && xx < Wn);
            const float* fp = feat + ((size_t)(b*Cn + icb))*HWn + yy*Wn + xx;
            #pragma unroll
            for (int j = 0; j < 16; j++) {
                float v = ok ? __ldg(fp + (size_t)j*HWn) : 0.f;
                __nv_bfloat16 h = __float2bfloat16(v);
                __nv_bfloat16 l = __float2bfloat16(v - __bfloat162float(h));
                int k = half * 16 + j;
                *reinterpret_cast<__nv_bfloat16*>(s + B_HI + k*272 + p*2) = h;
                *reinterpret_cast<__nv_bfloat16*>(s + B_LO + k*272 + p*2) = l;
            }
        } else {
            int hw = y * Wn + p;
            const float* offb = off + (size_t)b*27*HWn + hw;
            float offy = __ldg(offb + (size_t)(2*tap)*HWn);
            float offx = __ldg(offb + (size_t)(2*tap + 1)*HWn);
            float py = (float)(y + ky) + offy;
            float px = (float)(p + kx) + offx;
            float fy0 = floorf(py), fx0 = floorf(px);
            float ly = py - fy0, lx = px - fx0;
            bool vy0 = (fy0 >= 0.f)       && (fy0 <= 127.f);
            bool vy1 = (fy0 + 1.f >= 0.f) && (fy0 + 1.f <= 127.f);
            bool vx0 = (fx0 >= 0.f)       && (fx0 <= 127.f);
            bool vx1 = (fx0 + 1.f >= 0.f) && (fx0 + 1.f <= 127.f);
            float w00 = (1.f-ly)*(1.f-lx) * ((vy0 && vx0) ? 1.f : 0.f);
            float w01 = (1.f-ly)*lx       * ((vy0 && vx1) ? 1.f : 0.f);
            float w10 = ly*(1.f-lx)       * ((vy1 && vx0) ? 1.f : 0.f);
            float w11 = ly*lx             * ((vy1 && vx1) ? 1.f : 0.f);
            if (mode == 1) {
                float m = __ldg(offb + (size_t)(18 + tap)*HWn);
                w00 *= m; w01 *= m; w10 *= m; w11 *= m;
            }
            int iy0 = min(max((int)fy0,     0), Hn-1);
            int iy1 = min(max((int)fy0 + 1, 0), Hn-1);
            int ix0 = min(max((int)fx0,     0), Wn-1);
            int ix1 = min(max((int)fx0 + 1, 0), Wn-1);
            int i00 = iy0*Wn + ix0, i01 = iy0*Wn + ix1;
            int i10 = iy1*Wn + ix0, i11 = iy1*Wn + ix1;
            const float* fb = feat + ((size_t)(b*Cn + icb))*HWn;
            #pragma unroll
            for (int j = 0; j < 16; j++) {
                const float* f = fb + (size_t)j*HWn;
                float v = w00*__ldg(f + i00) + w01*__ldg(f + i01)
                        + w10*__ldg(f + i10) + w11*__ldg(f + i11);
                __nv_bfloat16 h = __float2bfloat16(v);
                __nv_bfloat16 l = __float2bfloat16(v - __bfloat162float(h));
                int k = half * 16 + j;
                *reinterpret_cast<__nv_bfloat16*>(s + B_HI + k*272 + p*2) = h;
                *reinterpret_cast<__nv_bfloat16*>(s + B_LO + k*272 + p*2) = l;
            }
        }
    };

    // ---- compute (lambda) ----
    auto compute = [&](int stg) {
        uint32_t sa_hi = sbase + stg*STG + A_HI + (uint32_t)(((m0 + aR)*40 + aC) * 2);
        uint32_t sa_lo = sa_hi + (A_LO - A_HI);
        uint32_t sb_hi = sbase + stg*STG + B_HI + (uint32_t)((bR*136 + n0 + bC) * 2);
        uint32_t sb_lo = sb_hi + (B_LO - B_HI);
        #pragma unroll
        for (int s2 = 0; s2 < 2; s2++) {
            uint32_t ah[2][4], al[2][4];
            ldsm4(ah[0], sa_hi + s2*32);
            ldsm4(ah[1], sa_hi + s2*32 + 16*80);
            ldsm4(al[0], sa_lo + s2*32);
            ldsm4(al[1], sa_lo + s2*32 + 16*80);
            #pragma unroll
            for (int nb = 0; nb < 4; nb++) {
                uint32_t bh[4], bl[4];
                ldsm4t(bh, sb_hi + s2*16*272 + nb*32);
                ldsm4t(bl, sb_lo + s2*16*272 + nb*32);
                #pragma unroll
                for (int mt = 0; mt < 2; mt++) {
                    mma16816(acc[mt*8 + 2*nb],     ah[mt], bh[0], bh[1]);
                    mma16816(acc[mt*8 + 2*nb + 1], ah[mt], bh[2], bh[3]);
                    mma16816(acc[mt*8 + 2*nb],     ah[mt], bl[0], bl[1]);
                    mma16816(acc[mt*8 + 2*nb + 1], ah[mt], bl[2], bl[3]);
                    mma16816(acc[mt*8 + 2*nb],     al[mt], bh[0], bh[1]);
                    mma16816(acc[mt*8 + 2*nb + 1], al[mt], bh[2], bh[3]);
                }
            }
        }
    };

    // ---- pipelined main loop ----
    load_chunk(0, 0);
    __syncthreads();
    for (int c = 0; c < NCHUNK; c++) {
        int cur = c & 1;
        if (c + 1 < NCHUNK) load_chunk(cur ^ 1, c + 1);
        compute(cur);
        __syncthreads();
    }

    // ---- epilogue ----
    const int r  = lane >> 2;
    const int c2 = (lane & 3) * 2;
    #pragma unroll
    for (int mt = 0; mt < 2; mt++) {
        int ocr = ocbase + m0 + mt*16 + r;
        float b0 = (mode == 0) ? __ldg(&bias[ocr])     : 0.f;
        float b1 = (mode == 0) ? __ldg(&bias[ocr + 8]) : 0.f;
        #pragma unroll
        for (int nt = 0; nt < 8; nt++) {
            float* d = acc[mt*8 + nt];
            int x = n0 + nt*8 + c2;
            float2 v0 = { fmaxf(d[0] + b0, 0.f), fmaxf(d[1] + b0, 0.f) };
            float2 v1 = { fmaxf(d[2] + b1, 0.f), fmaxf(d[3] + b1, 0.f) };
            size_t o0, o1;
            if (mode == 0) {
                o0 = ((size_t)(b*Cn + ocr))*HWn     + y*Wn + x;
                o1 = ((size_t)(b*Cn + ocr + 8))*HWn + y*Wn + x;
            } else {
                o0 = (size_t)ocr*NPIX       + (size_t)b*HWn + y*Wn + x;
                o1 = (size_t)(ocr + 8)*NPIX + (size_t)b*HWn + y*Wn + x;
            }
            *reinterpret_cast<float2*>(out + o0) = v0;
            *reinterpret_cast<float2*>(out + o1) = v1;
        }
    }
}

// ---------------- small kernels ----------------
__global__ void __launch_bounds__(256)
conv1x1_27_kernel(const float* __restrict__ in, const float* __restrict__ wgt,
                  const float* __restrict__ bias, float* __restrict__ out)
{
    __shared__ float ws[Cn*27];
    for (int idx = threadIdx.x; idx < Cn*27; idx += 256) {
        int o = idx >> 8, ic = idx & 255;
        ws[ic*27 + o] = wgt[(size_t)o*Cn + ic];
    }
    __syncthreads();
    int p  = blockIdx.x * 256 + threadIdx.x;
    int b  = p >> 14;
    int hw = p & (HWn - 1);
    float acc[27];
    #pragma unroll
    for (int o = 0; o < 27; o++) acc[o] = 0.f;
    const float* ip = in + (size_t)b*Cn*HWn + hw;
    for (int ic = 0; ic < Cn; ic++) {
        float v = __ldg(ip + (size_t)ic*HWn);
        #pragma unroll
        for (int o = 0; o < 27; o++) acc[o] += v * ws[ic*27 + o];
    }
    #pragma unroll
    for (int o = 0; o < 27; o++)
        out[((size_t)(b*27) + o)*HWn + hw] = acc[o] + bias[o];
}

__global__ void __launch_bounds__(256)
conv1x1_cls_kernel(const float* __restrict__ in, const float* __restrict__ wgt,
                   const float* __restrict__ bias, float* __restrict__ out)
{
    __shared__ float ws[Cn*16];
    int g = blockIdx.y;
    for (int idx = threadIdx.x; idx < Cn*16; idx += 256) {
        int j = idx >> 8, ic = idx & 255;
        ws[ic*16 + j] = wgt[(size_t)(g*16 + j)*Cn + ic];
    }
    __syncthreads();
    int p  = blockIdx.x * 256 + threadIdx.x;
    int b  = p >> 14;
    int hw = p & (HWn - 1);
    float acc[16];
    #pragma unroll
    for (int j = 0; j < 16; j++) acc[j] = 0.f;
    for (int ic = 0; ic < Cn; ic++) {
        float v = __ldg(&in[(size_t)ic*NPIX + p]);
        #pragma unroll
        for (int j = 0; j < 16; j++) acc[j] += v * ws[ic*16 + j];
    }
    #pragma unroll
    for (int j = 0; j < 16; j++) {
        int oc = g*16 + j;
        out[((size_t)(b*NCn) + oc)*HWn + hw] = acc[j] + bias[oc];
    }
}

__global__ void __launch_bounds__(256)
ref_fused_kernel(const float* __restrict__ in, const float* __restrict__ wgt,
                 const float* __restrict__ bias, const float* __restrict__ off,
                 float* __restrict__ dout)
{
    __shared__ float ws[Cn*18];
    for (int idx = threadIdx.x; idx < Cn*18; idx += 256) {
        int o = idx >> 8, ic = idx & 255;
        ws[ic*18 + o] = wgt[(size_t)o*Cn + ic];
    }
    __syncthreads();
    int p  = blockIdx.x * 256 + threadIdx.x;
    int b  = p >> 14;
    int hw = p & (HWn - 1);
    float acc[18];
    #pragma unroll
    for (int o = 0; o < 18; o++) acc[o] = 0.f;
    for (int ic = 0; ic < Cn; ic++) {
        float v = __ldg(&in[(size_t)ic*NPIX + p]);
        #pragma unroll
        for (int o = 0; o < 18; o++) acc[o] += v * ws[ic*18 + o];
    }
    float refine[18];
    #pragma unroll
    for (int o = 0; o < 18; o++)
        refine[o] = acc[o] + bias[o] + off[((size_t)(b*27) + o)*HWn + hw];
    float m0 = 0.f, m1 = 0.f;
    #pragma unroll
    for (int q = 0; q < 9; q++) { m0 += refine[2*q]; m1 += refine[2*q + 1]; }
    m0 *= (1.f/9.f); m1 *= (1.f/9.f);
    float wh0 = 0.f, wh1 = 0.f;
    #pragma unroll
    for (int q = 0; q < 9; q++) {
        wh0 = fmaxf(wh0, fabsf(refine[2*q]     + m0));
        wh1 = fmaxf(wh1, fabsf(refine[2*q + 1] + m1));
    }
    const size_t OUT_WH  = (size_t)Bn*NCn*HWn;
    const size_t OUT_REG = OUT_WH + (size_t)Bn*2*HWn;
    dout[OUT_WH  + ((size_t)(b*2) + 0)*HWn + hw] = wh0;
    dout[OUT_WH  + ((size_t)(b*2) + 1)*HWn + hw] = wh1;
    dout[OUT_REG + ((size_t)(b*2) + 0)*HWn + hw] = m0;
    dout[OUT_REG + ((size_t)(b*2) + 1)*HWn + hw] = m1;
}

// =====================================================================
extern "C" void kernel_launch(void* const* d_in, const int* in_sizes, int n_in,
                              void* d_out, int out_size)
{
    const float* x           = (const float*)d_in[0];
    const float* wconv[9]    = { (const float*)d_in[1],  (const float*)d_in[5],
                                 (const float*)d_in[9],  (const float*)d_in[3],
                                 (const float*)d_in[7],  (const float*)d_in[11],
                                 (const float*)d_in[13], (const float*)d_in[17],
                                 (const float*)d_in[20] };
    const float* cls_b0      = (const float*)d_in[2];
    const float* cls_b1      = (const float*)d_in[6];
    const float* cls_b2      = (const float*)d_in[10];
    const float* reg_b0      = (const float*)d_in[4];
    const float* reg_b1      = (const float*)d_in[8];
    const float* reg_b2      = (const float*)d_in[12];
    const float* init_conv_b = (const float*)d_in[14];
    const float* init_out_w  = (const float*)d_in[15];
    const float* init_out_b  = (const float*)d_in[16];
    const float* cls_out_w   = (const float*)d_in[18];
    const float* cls_out_b   = (const float*)d_in[19];
    const float* ref_out_w   = (const float*)d_in[21];
    const float* ref_out_b   = (const float*)d_in[22];
    float* out = (float*)d_out;

    float *bufA, *bufB, *cls, *pts, *off, *dcn;
    __nv_bfloat16 *whi, *wlo;
    cudaGetSymbolAddress((void**)&bufA, g_bufA);
    cudaGetSymbolAddress((void**)&bufB, g_bufB);
    cudaGetSymbolAddress((void**)&cls,  g_cls);
    cudaGetSymbolAddress((void**)&pts,  g_pts);
    cudaGetSymbolAddress((void**)&off,  g_off);
    cudaGetSymbolAddress((void**)&dcn,  g_dcn);
    cudaGetSymbolAddress((void**)&whi,  g_whi);
    cudaGetSymbolAddress((void**)&wlo,  g_wlo);

    cudaFuncSetAttribute(gemm_kernel, cudaFuncAttributeMaxDynamicSharedMemorySize, SM_TOTAL);

    // split all 9 conv/dcn weight tensors (order: cls0,cls1,cls2,reg0,reg1,reg2,init,dcn_cls,dcn_ref)
    for (int l = 0; l < 9; l++)
        split_w_kernel<<<Kdcn, 256>>>(wconv[l], whi + (size_t)l*WSZ, wlo + (size_t)l*WSZ);

    dim3 gg(256, 2);
    #define GEMM(md, in_, l, bias_, off_, out_) \
        gemm_kernel<<<gg, 256, SM_TOTAL>>>(md, in_, whi + (size_t)(l)*WSZ, \
                                           wlo + (size_t)(l)*WSZ, bias_, off_, out_)

    // cls tower
    GEMM(0, x,    0, cls_b0, nullptr, bufA);
    GEMM(0, bufA, 1, cls_b1, nullptr, bufB);
    GEMM(0, bufB, 2, cls_b2, nullptr, cls);
    // reg tower
    GEMM(0, x,    3, reg_b0, nullptr, bufA);
    GEMM(0, bufA, 4, reg_b1, nullptr, bufB);
    GEMM(0, bufB, 5, reg_b2, nullptr, pts);
    // init branch
    GEMM(0, pts,  6, init_conv_b, nullptr, bufA);
    conv1x1_27_kernel<<<128, 256>>>(bufA, init_out_w, init_out_b, off);

    // cls dcn (mask) -> cls head
    GEMM(1, cls, 7, nullptr, off, dcn);
    conv1x1_cls_kernel<<<dim3(128, 5), 256>>>(dcn, cls_out_w, cls_out_b, out);

    // ref dcn (no mask) -> fused refine/wh/reg
    GEMM(2, pts, 8, nullptr, off, dcn);
    ref_fused_kernel<<<128, 256>>>(dcn, ref_out_w, ref_out_b, off, out);
}